// round 1
// baseline (speedup 1.0000x reference)
#include <cuda_runtime.h>

// ---------------------------------------------------------------------------
// C_dense_24532853195160  —  fp32 baseline
//   h1 = lrelu(inputs @ W1 + b1)   [128,2048]
//   h2 = lrelu(h1 @ W2 + b2)       [128,1024]
//   h3 = lrelu(h2 @ W3 + b3)       [128,1024]
//   M  = h3 @ T.reshape(1024,10240)             [128,512,20]
//   ob[b,o] = sum_a exp(-sum_k |M[a,o,k]-M[b,o,k]|) - 1
//   out = [h3, ob] @ Wc + bc       [128,1]
// ---------------------------------------------------------------------------

#define BATCH 128
#define BM 64
#define BN 64
#define BK 16
#define TM 4
#define TN 4

// Scratch (allocation-free rule: __device__ globals)
__device__ float g_h1[BATCH * 2048];
__device__ float g_h2[BATCH * 1024];
__device__ float g_h3[BATCH * 1024];
__device__ float g_M [BATCH * 10240];
__device__ float g_ob[BATCH * 512];

// ---------------------------------------------------------------------------
// Tiled SGEMM: C[M,N] = A[M,K] @ B[K,N] (+bias) (+leakyrelu)
// All dims divisible by (BM,BN,BK) for this problem's shapes.
// 256 threads, each computes a 4x4 register tile of a 64x64 block tile.
// ---------------------------------------------------------------------------
__global__ __launch_bounds__(256) void gemm_bias_lrelu(
    const float* __restrict__ A, const float* __restrict__ B,
    const float* __restrict__ bias, float* __restrict__ C,
    int M, int N, int K, int apply_lrelu)
{
    __shared__ float As[BK][BM];
    __shared__ float Bs[BK][BN];

    const int tid = threadIdx.x;
    const int tx = tid & 15;        // 0..15
    const int ty = tid >> 4;        // 0..15
    const int row0 = blockIdx.y * BM;
    const int col0 = blockIdx.x * BN;

    float acc[TM][TN] = {};

    for (int k0 = 0; k0 < K; k0 += BK) {
        // A tile: 64 rows x 16 k, one float4 per thread, stored transposed
        {
            const int r  = tid >> 2;          // 0..63
            const int c4 = (tid & 3) << 2;    // 0,4,8,12
            float4 v = *reinterpret_cast<const float4*>(
                &A[(size_t)(row0 + r) * K + k0 + c4]);
            As[c4 + 0][r] = v.x;
            As[c4 + 1][r] = v.y;
            As[c4 + 2][r] = v.z;
            As[c4 + 3][r] = v.w;
        }
        // B tile: 16 k x 64 cols, one float4 per thread
        {
            const int r  = tid >> 4;          // 0..15
            const int c4 = (tid & 15) << 2;   // 0..60
            float4 v = *reinterpret_cast<const float4*>(
                &B[(size_t)(k0 + r) * N + col0 + c4]);
            *reinterpret_cast<float4*>(&Bs[r][c4]) = v;
        }
        __syncthreads();

        #pragma unroll
        for (int kk = 0; kk < BK; kk++) {
            float ra[TM], rb[TN];
            #pragma unroll
            for (int i = 0; i < TM; i++) ra[i] = As[kk][ty * TM + i];
            #pragma unroll
            for (int j = 0; j < TN; j++) rb[j] = Bs[kk][tx * TN + j];
            #pragma unroll
            for (int i = 0; i < TM; i++)
                #pragma unroll
                for (int j = 0; j < TN; j++)
                    acc[i][j] = fmaf(ra[i], rb[j], acc[i][j]);
        }
        __syncthreads();
    }

    #pragma unroll
    for (int i = 0; i < TM; i++) {
        const int r = row0 + ty * TM + i;
        #pragma unroll
        for (int j = 0; j < TN; j++) {
            const int c = col0 + tx * TN + j;
            float v = acc[i][j];
            if (bias) v += bias[c];
            if (apply_lrelu) v = (v >= 0.0f) ? v : 0.01f * v;
            C[(size_t)r * N + c] = v;
        }
    }
}

// ---------------------------------------------------------------------------
// Minibatch discrimination: one block per output column o (512 blocks).
// Shared holds M[:, o, :] (128 x 20). Thread b computes
//   ob[b,o] = sum_a exp(-sum_k |M[a,o,k]-M[b,o,k]|) - 1
// ---------------------------------------------------------------------------
__global__ __launch_bounds__(128) void mbd_kernel(
    const float* __restrict__ Mv, float* __restrict__ ob)
{
    const int o = blockIdx.x;        // 0..511
    const int b = threadIdx.x;       // 0..127
    __shared__ float Ms[BATCH * 20];

    #pragma unroll
    for (int i = 0; i < 20; i++) {
        int idx = b + i * BATCH;                 // 128*20 elems, 128 threads
        int a = idx / 20, k = idx % 20;
        Ms[a * 20 + k] = Mv[(size_t)a * 10240 + o * 20 + k];
    }
    __syncthreads();

    float my[20];
    #pragma unroll
    for (int k = 0; k < 20; k++) my[k] = Ms[b * 20 + k];

    float acc = 0.0f;
    for (int a = 0; a < BATCH; a++) {
        float s = 0.0f;
        #pragma unroll
        for (int k = 0; k < 20; k++)
            s += fabsf(Ms[a * 20 + k] - my[k]);
        acc += __expf(-s);
    }
    ob[(size_t)b * 512 + o] = acc - 1.0f;   // subtract self term exp(0)=1
}

// ---------------------------------------------------------------------------
// Final projection: out[b] = h3[b,:]·Wc[0:1024] + ob[b,:]·Wc[1024:1536] + bc
// One block per batch row.
// ---------------------------------------------------------------------------
__global__ __launch_bounds__(128) void final_kernel(
    const float* __restrict__ h3, const float* __restrict__ ob,
    const float* __restrict__ Wc, const float* __restrict__ bc,
    float* __restrict__ out)
{
    const int b = blockIdx.x;
    const int tid = threadIdx.x;

    float s = 0.0f;
    for (int j = tid; j < 1024; j += 128)
        s += h3[(size_t)b * 1024 + j] * Wc[j];
    for (int o = tid; o < 512; o += 128)
        s += ob[(size_t)b * 512 + o] * Wc[1024 + o];

    __shared__ float red[128];
    red[tid] = s;
    __syncthreads();
    #pragma unroll
    for (int st = 64; st > 0; st >>= 1) {
        if (tid < st) red[tid] += red[tid + st];
        __syncthreads();
    }
    if (tid == 0) out[b] = red[0] + bc[0];
}

// ---------------------------------------------------------------------------
// Launch
// ---------------------------------------------------------------------------
extern "C" void kernel_launch(void* const* d_in, const int* in_sizes, int n_in,
                              void* d_out, int out_size)
{
    const float* inputs = (const float*)d_in[0];  // [128,2048]
    const float* W1     = (const float*)d_in[1];  // [2048,2048]
    const float* b1     = (const float*)d_in[2];  // [2048]
    const float* W2     = (const float*)d_in[3];  // [2048,1024]
    const float* b2     = (const float*)d_in[4];  // [1024]
    const float* W3     = (const float*)d_in[5];  // [1024,1024]
    const float* b3     = (const float*)d_in[6];  // [1024]
    const float* T      = (const float*)d_in[7];  // [1024,512,20] -> [1024,10240]
    const float* Wc     = (const float*)d_in[8];  // [1536,1]
    const float* bc     = (const float*)d_in[9];  // [1]
    float* out = (float*)d_out;                   // [128,1]

    float *h1, *h2, *h3, *Mv, *ob;
    cudaGetSymbolAddress((void**)&h1, g_h1);
    cudaGetSymbolAddress((void**)&h2, g_h2);
    cudaGetSymbolAddress((void**)&h3, g_h3);
    cudaGetSymbolAddress((void**)&Mv, g_M);
    cudaGetSymbolAddress((void**)&ob, g_ob);

    dim3 blk(256);
    // GEMM1: [128,2048] @ [2048,2048]
    gemm_bias_lrelu<<<dim3(2048 / BN, BATCH / BM), blk>>>(
        inputs, W1, b1, h1, BATCH, 2048, 2048, 1);
    // GEMM2: [128,2048] @ [2048,1024]
    gemm_bias_lrelu<<<dim3(1024 / BN, BATCH / BM), blk>>>(
        h1, W2, b2, h2, BATCH, 1024, 2048, 1);
    // GEMM3: [128,1024] @ [1024,1024]
    gemm_bias_lrelu<<<dim3(1024 / BN, BATCH / BM), blk>>>(
        h2, W3, b3, h3, BATCH, 1024, 1024, 1);
    // GEMM4 (no bias/act): [128,1024] @ [1024,10240]
    gemm_bias_lrelu<<<dim3(10240 / BN, BATCH / BM), blk>>>(
        h3, T, nullptr, Mv, BATCH, 10240, 1024, 0);
    // Minibatch discrimination
    mbd_kernel<<<512, 128>>>(Mv, ob);
    // Final projection
    final_kernel<<<BATCH, 128>>>(h3, ob, Wc, bc, out);
}

// round 3
// speedup vs baseline: 2.8823x; 2.8823x over previous
#include <cuda_runtime.h>
#include <cuda_bf16.h>
#include <cstdint>

#define BATCH 128

// ---------------- scratch (__device__ globals: allocation-free rule) -------
__device__ float g_h1[BATCH * 2048];
__device__ float g_h2[BATCH * 1024];
__device__ float g_h3[BATCH * 1024];
__device__ float g_M [BATCH * 10240];
__device__ float g_ob[BATCH * 512];
// split-K partial buffers
__device__ float g_p1[8  * BATCH * 2048];
__device__ float g_p2[16 * BATCH * 1024];
__device__ float g_p3[16 * BATCH * 1024];
__device__ float g_p4[2  * BATCH * 10240];

// ---------------- helpers ---------------------------------------------------
__device__ __forceinline__ uint32_t smem_u32(const void* p) {
    uint32_t a;
    asm("{ .reg .u64 t; cvta.to.shared.u64 t, %1; cvt.u32.u64 %0, t; }"
        : "=r"(a) : "l"(p));
    return a;
}

__device__ __forceinline__ void ldsm_x4(uint32_t* r, uint32_t addr) {
    asm volatile("ldmatrix.sync.aligned.m8n8.x4.shared.b16 {%0,%1,%2,%3}, [%4];"
        : "=r"(r[0]), "=r"(r[1]), "=r"(r[2]), "=r"(r[3]) : "r"(addr));
}
__device__ __forceinline__ void ldsm_x4_t(uint32_t* r, uint32_t addr) {
    asm volatile("ldmatrix.sync.aligned.m8n8.x4.trans.shared.b16 {%0,%1,%2,%3}, [%4];"
        : "=r"(r[0]), "=r"(r[1]), "=r"(r[2]), "=r"(r[3]) : "r"(addr));
}
__device__ __forceinline__ void mma16816(float* d, const uint32_t* a,
                                         uint32_t b0, uint32_t b1) {
    asm volatile(
        "mma.sync.aligned.m16n8k16.row.col.f32.bf16.bf16.f32 "
        "{%0,%1,%2,%3}, {%4,%5,%6,%7}, {%8,%9}, {%0,%1,%2,%3};"
        : "+f"(d[0]), "+f"(d[1]), "+f"(d[2]), "+f"(d[3])
        : "r"(a[0]), "r"(a[1]), "r"(a[2]), "r"(a[3]), "r"(b0), "r"(b1));
}

__device__ __forceinline__ uint32_t pack_hi(float f0, float f1) {
    __nv_bfloat16 b0 = __float2bfloat16(f0);
    __nv_bfloat16 b1 = __float2bfloat16(f1);
    return ((uint32_t)__bfloat16_as_ushort(b1) << 16) | __bfloat16_as_ushort(b0);
}
__device__ __forceinline__ uint32_t pack_lo(float f0, float f1) {
    __nv_bfloat16 b0 = __float2bfloat16(f0);
    __nv_bfloat16 b1 = __float2bfloat16(f1);
    __nv_bfloat16 c0 = __float2bfloat16(f0 - __bfloat162float(b0));
    __nv_bfloat16 c1 = __float2bfloat16(f1 - __bfloat162float(b1));
    return ((uint32_t)__bfloat16_as_ushort(c1) << 16) | __bfloat16_as_ushort(c0);
}

// ---------------- GEMM via mma.sync (bf16, split-K partials) ---------------
// part[split, 128, Ncols] += act[128, kSlice] @ W[kSlice, Ncols-tile]
// CTA tile: full M=128 x 128 cols. 8 warps: 4(m) x 2(n), warp tile 32x64.
static constexpr int AS_STR = 72;                 // bf16 elems/row (pad: 144B)
static constexpr int BS_STR = 136;                // bf16 elems/row (pad: 272B)
static constexpr int AS_BYTES = 128 * AS_STR * 2; // 18432
static constexpr int BS_BYTES = 64 * BS_STR * 2;  // 17408
static constexpr int SMEM_SZ  = 2 * AS_BYTES + 2 * BS_BYTES; // 71680

__global__ __launch_bounds__(256, 1)
void mma_gemm(const float* __restrict__ act, const float* __restrict__ W,
              float* __restrict__ part, int Ncols, int K, int kLen, int three)
{
    extern __shared__ __align__(128) char sm[];
    __nv_bfloat16* AsHi = (__nv_bfloat16*)(sm);
    __nv_bfloat16* AsLo = (__nv_bfloat16*)(sm + AS_BYTES);
    __nv_bfloat16* BsHi = (__nv_bfloat16*)(sm + 2 * AS_BYTES);
    __nv_bfloat16* BsLo = (__nv_bfloat16*)(sm + 2 * AS_BYTES + BS_BYTES);

    const int tid  = threadIdx.x;
    const int lane = tid & 31;
    const int wid  = tid >> 5;
    const int wm   = (wid & 3) * 32;   // warp row base (m)
    const int wn   = (wid >> 2) * 64;  // warp col base (n, within 128 tile)
    const int n0     = blockIdx.x * 128;
    const int kStart = blockIdx.y * kLen;

    float acc[2][8][4];
    #pragma unroll
    for (int i = 0; i < 2; i++)
        #pragma unroll
        for (int j = 0; j < 8; j++)
            #pragma unroll
            for (int c = 0; c < 4; c++) acc[i][j][c] = 0.0f;

    const uint32_t asHiB = smem_u32(AsHi), asLoB = smem_u32(AsLo);
    const uint32_t bsHiB = smem_u32(BsHi), bsLoB = smem_u32(BsLo);

    for (int k0 = 0; k0 < kLen; k0 += 64) {
        // ---- stage A: act[128, 64] -> hi/lo bf16 smem ----
        {
            const int row = tid >> 1;
            const int seg = (tid & 1) * 32;
            const float4* src = (const float4*)(act + (size_t)row * K + kStart + k0 + seg);
            float f[32];
            #pragma unroll
            for (int j = 0; j < 8; j++) *(float4*)(f + 4 * j) = src[j];
            uint32_t hi[16], lo[16];
            #pragma unroll
            for (int w = 0; w < 16; w++) hi[w] = pack_hi(f[2*w], f[2*w+1]);
            uint4* dh = (uint4*)(AsHi + row * AS_STR + seg);
            #pragma unroll
            for (int i = 0; i < 4; i++)
                dh[i] = make_uint4(hi[4*i], hi[4*i+1], hi[4*i+2], hi[4*i+3]);
            if (three) {
                #pragma unroll
                for (int w = 0; w < 16; w++) lo[w] = pack_lo(f[2*w], f[2*w+1]);
                uint4* dl = (uint4*)(AsLo + row * AS_STR + seg);
                #pragma unroll
                for (int i = 0; i < 4; i++)
                    dl[i] = make_uint4(lo[4*i], lo[4*i+1], lo[4*i+2], lo[4*i+3]);
            }
        }
        // ---- stage B: W[64, 128] -> hi/lo bf16 smem ----
        {
            const int r   = tid >> 2;
            const int seg = (tid & 3) * 32;
            const float4* src = (const float4*)(W + (size_t)(kStart + k0 + r) * Ncols + n0 + seg);
            float f[32];
            #pragma unroll
            for (int j = 0; j < 8; j++) *(float4*)(f + 4 * j) = src[j];
            uint32_t hi[16], lo[16];
            #pragma unroll
            for (int w = 0; w < 16; w++) hi[w] = pack_hi(f[2*w], f[2*w+1]);
            uint4* dh = (uint4*)(BsHi + r * BS_STR + seg);
            #pragma unroll
            for (int i = 0; i < 4; i++)
                dh[i] = make_uint4(hi[4*i], hi[4*i+1], hi[4*i+2], hi[4*i+3]);
            if (three) {
                #pragma unroll
                for (int w = 0; w < 16; w++) lo[w] = pack_lo(f[2*w], f[2*w+1]);
                uint4* dl = (uint4*)(BsLo + r * BS_STR + seg);
                #pragma unroll
                for (int i = 0; i < 4; i++)
                    dl[i] = make_uint4(lo[4*i], lo[4*i+1], lo[4*i+2], lo[4*i+3]);
            }
        }
        __syncthreads();

        // ---- compute: 4 k-steps of 16 ----
        #pragma unroll
        for (int kk = 0; kk < 64; kk += 16) {
            const uint32_t arow = wm + (lane & 15);
            const uint32_t acol = kk + ((lane >> 4) << 3);
            uint32_t ah[2][4], al[2][4];
            #pragma unroll
            for (int mt = 0; mt < 2; mt++) {
                uint32_t off = ((arow + mt * 16) * AS_STR + acol) * 2;
                ldsm_x4(ah[mt], asHiB + off);
                if (three) ldsm_x4(al[mt], asLoB + off);
            }
            uint32_t bh[8][2], bl[8][2];
            #pragma unroll
            for (int np = 0; np < 4; np++) {
                const uint32_t brow = kk + (lane & 15);
                const uint32_t bcol = wn + np * 16 + ((lane >> 4) << 3);
                uint32_t off = (brow * BS_STR + bcol) * 2;
                uint32_t r4[4];
                ldsm_x4_t(r4, bsHiB + off);
                bh[np*2][0] = r4[0]; bh[np*2][1] = r4[1];
                bh[np*2+1][0] = r4[2]; bh[np*2+1][1] = r4[3];
                if (three) {
                    ldsm_x4_t(r4, bsLoB + off);
                    bl[np*2][0] = r4[0]; bl[np*2][1] = r4[1];
                    bl[np*2+1][0] = r4[2]; bl[np*2+1][1] = r4[3];
                }
            }
            #pragma unroll
            for (int mt = 0; mt < 2; mt++)
                #pragma unroll
                for (int nt = 0; nt < 8; nt++) {
                    mma16816(acc[mt][nt], ah[mt], bh[nt][0], bh[nt][1]);
                    if (three) {
                        mma16816(acc[mt][nt], ah[mt], bl[nt][0], bl[nt][1]);
                        mma16816(acc[mt][nt], al[mt], bh[nt][0], bh[nt][1]);
                    }
                }
        }
        __syncthreads();
    }

    // ---- store partial tile ----
    {
        float* pbase = part + (size_t)blockIdx.y * BATCH * (size_t)Ncols;
        const int g  = lane >> 2;
        const int c2 = (lane & 3) * 2;
        #pragma unroll
        for (int mt = 0; mt < 2; mt++)
            #pragma unroll
            for (int nt = 0; nt < 8; nt++) {
                const int m = wm + mt * 16 + g;
                const int n = n0 + wn + nt * 8 + c2;
                float2 v0 = make_float2(acc[mt][nt][0], acc[mt][nt][1]);
                float2 v1 = make_float2(acc[mt][nt][2], acc[mt][nt][3]);
                *(float2*)&pbase[(size_t)m * Ncols + n] = v0;
                *(float2*)&pbase[(size_t)(m + 8) * Ncols + n] = v1;
            }
    }
}

// ---------------- split-K reduce + bias + LeakyReLU ------------------------
__global__ __launch_bounds__(256)
void reduce_bias_act(const float* __restrict__ part, const float* __restrict__ bias,
                     float* __restrict__ out, int Ncols, int S, int lrelu)
{
    const int i4 = blockIdx.x * 256 + threadIdx.x;     // float4 index
    const int E4 = BATCH * Ncols / 4;
    if (i4 >= E4) return;
    const float4* p4 = (const float4*)part;
    float4 s = p4[i4];
    for (int sp = 1; sp < S; sp++) {
        float4 t = p4[(size_t)sp * E4 + i4];
        s.x += t.x; s.y += t.y; s.z += t.z; s.w += t.w;
    }
    if (bias) {
        const int col = (i4 * 4) % Ncols;
        s.x += bias[col]; s.y += bias[col+1]; s.z += bias[col+2]; s.w += bias[col+3];
    }
    if (lrelu) {
        s.x = (s.x >= 0.f) ? s.x : 0.01f * s.x;
        s.y = (s.y >= 0.f) ? s.y : 0.01f * s.y;
        s.z = (s.z >= 0.f) ? s.z : 0.01f * s.z;
        s.w = (s.w >= 0.f) ? s.w : 0.01f * s.w;
    }
    ((float4*)out)[i4] = s;
}

// ---------------- minibatch discrimination ---------------------------------
__global__ __launch_bounds__(128) void mbd_kernel(
    const float* __restrict__ Mv, float* __restrict__ ob)
{
    const int o = blockIdx.x;
    const int b = threadIdx.x;
    __shared__ float Ms[BATCH * 20];

    #pragma unroll
    for (int i = 0; i < 20; i++) {
        int idx = b + i * BATCH;
        int a = idx / 20, k = idx % 20;
        Ms[a * 20 + k] = Mv[(size_t)a * 10240 + o * 20 + k];
    }
    __syncthreads();

    float my[20];
    #pragma unroll
    for (int k = 0; k < 20; k++) my[k] = Ms[b * 20 + k];

    float acc = 0.0f;
    for (int a = 0; a < BATCH; a++) {
        float s = 0.0f;
        #pragma unroll
        for (int k = 0; k < 20; k++)
            s += fabsf(Ms[a * 20 + k] - my[k]);
        acc += __expf(-s);
    }
    ob[(size_t)b * 512 + o] = acc - 1.0f;
}

__global__ __launch_bounds__(128) void final_kernel(
    const float* __restrict__ h3, const float* __restrict__ ob,
    const float* __restrict__ Wc, const float* __restrict__ bc,
    float* __restrict__ out)
{
    const int b = blockIdx.x;
    const int tid = threadIdx.x;

    float s = 0.0f;
    for (int j = tid; j < 1024; j += 128)
        s += h3[(size_t)b * 1024 + j] * Wc[j];
    for (int o = tid; o < 512; o += 128)
        s += ob[(size_t)b * 512 + o] * Wc[1024 + o];

    __shared__ float red[128];
    red[tid] = s;
    __syncthreads();
    #pragma unroll
    for (int st = 64; st > 0; st >>= 1) {
        if (tid < st) red[tid] += red[tid + st];
        __syncthreads();
    }
    if (tid == 0) out[b] = red[0] + bc[0];
}

// ---------------------------------------------------------------------------
extern "C" void kernel_launch(void* const* d_in, const int* in_sizes, int n_in,
                              void* d_out, int out_size)
{
    const float* inputs = (const float*)d_in[0];
    const float* W1     = (const float*)d_in[1];
    const float* b1     = (const float*)d_in[2];
    const float* W2     = (const float*)d_in[3];
    const float* b2     = (const float*)d_in[4];
    const float* W3     = (const float*)d_in[5];
    const float* b3     = (const float*)d_in[6];
    const float* T      = (const float*)d_in[7];
    const float* Wc     = (const float*)d_in[8];
    const float* bc     = (const float*)d_in[9];
    float* out = (float*)d_out;

    float *h1, *h2, *h3, *Mv, *ob, *p1, *p2, *p3, *p4;
    cudaGetSymbolAddress((void**)&h1, g_h1);
    cudaGetSymbolAddress((void**)&h2, g_h2);
    cudaGetSymbolAddress((void**)&h3, g_h3);
    cudaGetSymbolAddress((void**)&Mv, g_M);
    cudaGetSymbolAddress((void**)&ob, g_ob);
    cudaGetSymbolAddress((void**)&p1, g_p1);
    cudaGetSymbolAddress((void**)&p2, g_p2);
    cudaGetSymbolAddress((void**)&p3, g_p3);
    cudaGetSymbolAddress((void**)&p4, g_p4);

    cudaFuncSetAttribute(mma_gemm, cudaFuncAttributeMaxDynamicSharedMemorySize, SMEM_SZ);

    // GEMM1: [128,2048]@[2048,2048]  (16 n-tiles x 8 splits, kLen=256, 3-pass)
    mma_gemm<<<dim3(16, 8), 256, SMEM_SZ>>>(inputs, W1, p1, 2048, 2048, 256, 1);
    reduce_bias_act<<<(BATCH * 2048 / 4 + 255) / 256, 256>>>(p1, b1, h1, 2048, 8, 1);

    // GEMM2: [128,2048]@[2048,1024]  (8 x 16 splits, kLen=128)
    mma_gemm<<<dim3(8, 16), 256, SMEM_SZ>>>(h1, W2, p2, 1024, 2048, 128, 1);
    reduce_bias_act<<<(BATCH * 1024 / 4 + 255) / 256, 256>>>(p2, b2, h2, 1024, 16, 1);

    // GEMM3: [128,1024]@[1024,1024]  (8 x 16 splits, kLen=64)
    mma_gemm<<<dim3(8, 16), 256, SMEM_SZ>>>(h2, W3, p3, 1024, 1024, 64, 1);
    reduce_bias_act<<<(BATCH * 1024 / 4 + 255) / 256, 256>>>(p3, b3, h3, 1024, 16, 1);

    // GEMM4: [128,1024]@[1024,10240]  (80 x 2 splits, kLen=512, single-pass bf16)
    mma_gemm<<<dim3(80, 2), 256, SMEM_SZ>>>(h3, T, p4, 10240, 1024, 512, 0);
    reduce_bias_act<<<(BATCH * 10240 / 4 + 255) / 256, 256>>>(p4, nullptr, Mv, 10240, 2, 0);

    mbd_kernel<<<512, 128>>>(Mv, ob);
    final_kernel<<<BATCH, 128>>>(h3, ob, Wc, bc, out);
}

// round 4
// speedup vs baseline: 2.9191x; 1.0128x over previous
#include <cuda_runtime.h>
#include <cuda_bf16.h>
#include <cstdint>

#define BATCH 128

// ---------------- scratch (__device__ globals) ------------------------------
__device__ float g_h1[BATCH * 2048];
__device__ float g_h2[BATCH * 1024];
__device__ float g_h3[BATCH * 1024];
__device__ float g_M [BATCH * 10240];
__device__ float g_ob[BATCH * 512];
__device__ float g_p1[4 * BATCH * 2048];
__device__ float g_p2[8 * BATCH * 1024];
__device__ float g_p3[8 * BATCH * 1024];

// ---------------- helpers ----------------------------------------------------
__device__ __forceinline__ uint32_t smem_u32(const void* p) {
    uint32_t a;
    asm("{ .reg .u64 t; cvta.to.shared.u64 t, %1; cvt.u32.u64 %0, t; }"
        : "=r"(a) : "l"(p));
    return a;
}
__device__ __forceinline__ void ldsm_x4(uint32_t* r, uint32_t addr) {
    asm volatile("ldmatrix.sync.aligned.m8n8.x4.shared.b16 {%0,%1,%2,%3}, [%4];"
        : "=r"(r[0]), "=r"(r[1]), "=r"(r[2]), "=r"(r[3]) : "r"(addr));
}
__device__ __forceinline__ void ldsm_x4_t(uint32_t* r, uint32_t addr) {
    asm volatile("ldmatrix.sync.aligned.m8n8.x4.trans.shared.b16 {%0,%1,%2,%3}, [%4];"
        : "=r"(r[0]), "=r"(r[1]), "=r"(r[2]), "=r"(r[3]) : "r"(addr));
}
__device__ __forceinline__ void mma16816(float* d, const uint32_t* a,
                                         uint32_t b0, uint32_t b1) {
    asm volatile(
        "mma.sync.aligned.m16n8k16.row.col.f32.bf16.bf16.f32 "
        "{%0,%1,%2,%3}, {%4,%5,%6,%7}, {%8,%9}, {%0,%1,%2,%3};"
        : "+f"(d[0]), "+f"(d[1]), "+f"(d[2]), "+f"(d[3])
        : "r"(a[0]), "r"(a[1]), "r"(a[2]), "r"(a[3]), "r"(b0), "r"(b1));
}
__device__ __forceinline__ uint32_t pack_hi(float f0, float f1) {
    __nv_bfloat16 b0 = __float2bfloat16(f0);
    __nv_bfloat16 b1 = __float2bfloat16(f1);
    return ((uint32_t)__bfloat16_as_ushort(b1) << 16) | __bfloat16_as_ushort(b0);
}
__device__ __forceinline__ uint32_t pack_lo(float f0, float f1) {
    __nv_bfloat16 b0 = __float2bfloat16(f0);
    __nv_bfloat16 b1 = __float2bfloat16(f1);
    __nv_bfloat16 c0 = __float2bfloat16(f0 - __bfloat162float(b0));
    __nv_bfloat16 c1 = __float2bfloat16(f1 - __bfloat162float(b1));
    return ((uint32_t)__bfloat16_as_ushort(c1) << 16) | __bfloat16_as_ushort(c0);
}

// ---------------- GEMM: CTA tile M=128 x N=64, BK=64, 2-stage pipeline ------
static constexpr int AS_STR  = 72;                    // bf16 elems / row
static constexpr int BS_STR  = 72;
static constexpr int AS_B    = 128 * AS_STR * 2;      // 18432
static constexpr int BS_B    = 64 * BS_STR * 2;       // 9216
static constexpr int STAGE_B = 2 * AS_B + 2 * BS_B;   // 55296
static constexpr int SMEM_SZ = 2 * STAGE_B;           // 110592

template <int THREE>
__global__ __launch_bounds__(256, 1)
void mma_gemm(const float* __restrict__ act, const float* __restrict__ W,
              float* __restrict__ outp, const float* __restrict__ bias,
              int Ncols, int K, int kLen, int fuse, int lrelu)
{
    extern __shared__ __align__(128) char sm[];
    const int tid  = threadIdx.x;
    const int lane = tid & 31;
    const int wid  = tid >> 5;
    const int wm   = (wid & 3) * 32;
    const int wn   = (wid >> 2) * 32;
    const int n0     = blockIdx.x * 64;
    const int kStart = blockIdx.y * kLen;
    const int nIter  = kLen >> 6;

    const int aRow = tid >> 1, aSeg = (tid & 1) * 32;
    const int bRow = tid >> 2, bSeg = (tid & 3) * 16;
    const float* aPtr = act + (size_t)aRow * K + kStart + aSeg;

    float fa[32], fb[16];

    auto LOAD = [&](int it) {
        const float4* s = (const float4*)(aPtr + it * 64);
        #pragma unroll
        for (int j = 0; j < 8; j++) *(float4*)(fa + 4 * j) = s[j];
        const float4* t = (const float4*)(W + (size_t)(kStart + it * 64 + bRow) * Ncols
                                          + n0 + bSeg);
        #pragma unroll
        for (int j = 0; j < 4; j++) *(float4*)(fb + 4 * j) = t[j];
    };

    auto STORE = [&](int st) {
        char* base = sm + st * STAGE_B;
        {
            uint32_t h[16];
            #pragma unroll
            for (int w = 0; w < 16; w++) h[w] = pack_hi(fa[2*w], fa[2*w+1]);
            uint4* d = (uint4*)((__nv_bfloat16*)base + aRow * AS_STR + aSeg);
            #pragma unroll
            for (int i = 0; i < 4; i++)
                d[i] = make_uint4(h[4*i], h[4*i+1], h[4*i+2], h[4*i+3]);
            if (THREE) {
                uint32_t l[16];
                #pragma unroll
                for (int w = 0; w < 16; w++) l[w] = pack_lo(fa[2*w], fa[2*w+1]);
                uint4* dl = (uint4*)((__nv_bfloat16*)(base + AS_B) + aRow * AS_STR + aSeg);
                #pragma unroll
                for (int i = 0; i < 4; i++)
                    dl[i] = make_uint4(l[4*i], l[4*i+1], l[4*i+2], l[4*i+3]);
            }
        }
        {
            uint32_t h[8];
            #pragma unroll
            for (int w = 0; w < 8; w++) h[w] = pack_hi(fb[2*w], fb[2*w+1]);
            uint4* d = (uint4*)((__nv_bfloat16*)(base + 2 * AS_B) + bRow * BS_STR + bSeg);
            d[0] = make_uint4(h[0], h[1], h[2], h[3]);
            d[1] = make_uint4(h[4], h[5], h[6], h[7]);
            if (THREE) {
                uint32_t l[8];
                #pragma unroll
                for (int w = 0; w < 8; w++) l[w] = pack_lo(fb[2*w], fb[2*w+1]);
                uint4* dl = (uint4*)((__nv_bfloat16*)(base + 2 * AS_B + BS_B)
                                     + bRow * BS_STR + bSeg);
                dl[0] = make_uint4(l[0], l[1], l[2], l[3]);
                dl[1] = make_uint4(l[4], l[5], l[6], l[7]);
            }
        }
    };

    float acc[2][4][4];
    #pragma unroll
    for (int i = 0; i < 2; i++)
        #pragma unroll
        for (int j = 0; j < 4; j++)
            #pragma unroll
            for (int c = 0; c < 4; c++) acc[i][j][c] = 0.0f;

    LOAD(0);
    STORE(0);
    __syncthreads();

    for (int it = 0; it < nIter; ++it) {
        const int st = it & 1;
        const bool more = (it + 1 < nIter);
        if (more) LOAD(it + 1);                       // LDG in flight over MMAs

        const uint32_t asHi = smem_u32(sm + st * STAGE_B);
        const uint32_t asLo = asHi + AS_B;
        const uint32_t bsHi = asHi + 2 * AS_B;
        const uint32_t bsLo = bsHi + BS_B;

        #pragma unroll
        for (int kk = 0; kk < 64; kk += 16) {
            const uint32_t arow = wm + (lane & 15);
            const uint32_t acol = kk + ((lane >> 4) << 3);
            uint32_t ah[2][4], al[2][4];
            #pragma unroll
            for (int mt = 0; mt < 2; mt++) {
                uint32_t off = ((arow + mt * 16) * AS_STR + acol) * 2;
                ldsm_x4(ah[mt], asHi + off);
                if (THREE) ldsm_x4(al[mt], asLo + off);
            }
            uint32_t bh[4][2], bl[4][2];
            #pragma unroll
            for (int np = 0; np < 2; np++) {
                const uint32_t brow = kk + (lane & 15);
                const uint32_t bcol = wn + np * 16 + ((lane >> 4) << 3);
                uint32_t off = (brow * BS_STR + bcol) * 2;
                uint32_t r4[4];
                ldsm_x4_t(r4, bsHi + off);
                bh[np*2][0] = r4[0]; bh[np*2][1] = r4[1];
                bh[np*2+1][0] = r4[2]; bh[np*2+1][1] = r4[3];
                if (THREE) {
                    ldsm_x4_t(r4, bsLo + off);
                    bl[np*2][0] = r4[0]; bl[np*2][1] = r4[1];
                    bl[np*2+1][0] = r4[2]; bl[np*2+1][1] = r4[3];
                }
            }
            #pragma unroll
            for (int mt = 0; mt < 2; mt++)
                #pragma unroll
                for (int nt = 0; nt < 4; nt++) {
                    mma16816(acc[mt][nt], ah[mt], bh[nt][0], bh[nt][1]);
                    if (THREE) {
                        mma16816(acc[mt][nt], ah[mt], bl[nt][0], bl[nt][1]);
                        mma16816(acc[mt][nt], al[mt], bh[nt][0], bh[nt][1]);
                    }
                }
        }

        if (more) STORE((it + 1) & 1);                // different buffer: no race
        __syncthreads();
    }

    // ---- epilogue ----
    float* pbase = fuse ? outp
                        : outp + (size_t)blockIdx.y * BATCH * (size_t)Ncols;
    const int g  = lane >> 2;
    const int c2 = (lane & 3) * 2;
    #pragma unroll
    for (int mt = 0; mt < 2; mt++)
        #pragma unroll
        for (int nt = 0; nt < 4; nt++) {
            const int m = wm + mt * 16 + g;
            const int n = n0 + wn + nt * 8 + c2;
            float v0 = acc[mt][nt][0], v1 = acc[mt][nt][1];
            float v2 = acc[mt][nt][2], v3 = acc[mt][nt][3];
            if (fuse) {
                if (bias) { float b0 = bias[n], b1 = bias[n+1];
                            v0 += b0; v1 += b1; v2 += b0; v3 += b1; }
                if (lrelu) {
                    v0 = (v0 >= 0.f) ? v0 : 0.01f * v0;
                    v1 = (v1 >= 0.f) ? v1 : 0.01f * v1;
                    v2 = (v2 >= 0.f) ? v2 : 0.01f * v2;
                    v3 = (v3 >= 0.f) ? v3 : 0.01f * v3;
                }
            }
            *(float2*)&pbase[(size_t)m * Ncols + n]       = make_float2(v0, v1);
            *(float2*)&pbase[(size_t)(m + 8) * Ncols + n] = make_float2(v2, v3);
        }
}

// ---------------- split-K reduce + bias + LeakyReLU (S compile-time) --------
template <int S>
__global__ __launch_bounds__(256)
void reduce_bias_act(const float* __restrict__ part, const float* __restrict__ bias,
                     float* __restrict__ out, int Ncols, int lrelu)
{
    const int i4 = blockIdx.x * 256 + threadIdx.x;
    const int E4 = BATCH * Ncols / 4;
    if (i4 >= E4) return;
    const float4* p4 = (const float4*)part;
    float4 v[S];
    #pragma unroll
    for (int sp = 0; sp < S; sp++) v[sp] = p4[(size_t)sp * E4 + i4];
    float4 s = v[0];
    #pragma unroll
    for (int sp = 1; sp < S; sp++) {
        s.x += v[sp].x; s.y += v[sp].y; s.z += v[sp].z; s.w += v[sp].w;
    }
    const int col = (i4 * 4) % Ncols;
    s.x += bias[col]; s.y += bias[col+1]; s.z += bias[col+2]; s.w += bias[col+3];
    if (lrelu) {
        s.x = (s.x >= 0.f) ? s.x : 0.01f * s.x;
        s.y = (s.y >= 0.f) ? s.y : 0.01f * s.y;
        s.z = (s.z >= 0.f) ? s.z : 0.01f * s.z;
        s.w = (s.w >= 0.f) ? s.w : 0.01f * s.w;
    }
    ((float4*)out)[i4] = s;
}

// ---------------- minibatch discrimination ----------------------------------
__global__ __launch_bounds__(128) void mbd_kernel(
    const float* __restrict__ Mv, float* __restrict__ ob)
{
    const int o = blockIdx.x;
    const int b = threadIdx.x;
    __shared__ float Ms[BATCH * 20];

    #pragma unroll
    for (int i = 0; i < 20; i++) {
        int idx = b + i * BATCH;
        int a = idx / 20, k = idx % 20;
        Ms[a * 20 + k] = Mv[(size_t)a * 10240 + o * 20 + k];
    }
    __syncthreads();

    float my[20];
    #pragma unroll
    for (int k = 0; k < 20; k++) my[k] = Ms[b * 20 + k];

    float acc = 0.0f;
    for (int a = 0; a < BATCH; a++) {
        float s = 0.0f;
        #pragma unroll
        for (int k = 0; k < 20; k++)
            s += fabsf(Ms[a * 20 + k] - my[k]);
        acc += __expf(-s);
    }
    ob[(size_t)b * 512 + o] = acc - 1.0f;
}

__global__ __launch_bounds__(128) void final_kernel(
    const float* __restrict__ h3, const float* __restrict__ ob,
    const float* __restrict__ Wc, const float* __restrict__ bc,
    float* __restrict__ out)
{
    const int b = blockIdx.x;
    const int tid = threadIdx.x;

    float s = 0.0f;
    for (int j = tid; j < 1024; j += 128)
        s += h3[(size_t)b * 1024 + j] * Wc[j];
    for (int o = tid; o < 512; o += 128)
        s += ob[(size_t)b * 512 + o] * Wc[1024 + o];

    __shared__ float red[128];
    red[tid] = s;
    __syncthreads();
    #pragma unroll
    for (int st = 64; st > 0; st >>= 1) {
        if (tid < st) red[tid] += red[tid + st];
        __syncthreads();
    }
    if (tid == 0) out[b] = red[0] + bc[0];
}

// ---------------------------------------------------------------------------
extern "C" void kernel_launch(void* const* d_in, const int* in_sizes, int n_in,
                              void* d_out, int out_size)
{
    const float* inputs = (const float*)d_in[0];
    const float* W1     = (const float*)d_in[1];
    const float* b1     = (const float*)d_in[2];
    const float* W2     = (const float*)d_in[3];
    const float* b2     = (const float*)d_in[4];
    const float* W3     = (const float*)d_in[5];
    const float* b3     = (const float*)d_in[6];
    const float* T      = (const float*)d_in[7];
    const float* Wc     = (const float*)d_in[8];
    const float* bc     = (const float*)d_in[9];
    float* out = (float*)d_out;

    float *h1, *h2, *h3, *Mv, *ob, *p1, *p2, *p3;
    cudaGetSymbolAddress((void**)&h1, g_h1);
    cudaGetSymbolAddress((void**)&h2, g_h2);
    cudaGetSymbolAddress((void**)&h3, g_h3);
    cudaGetSymbolAddress((void**)&Mv, g_M);
    cudaGetSymbolAddress((void**)&ob, g_ob);
    cudaGetSymbolAddress((void**)&p1, g_p1);
    cudaGetSymbolAddress((void**)&p2, g_p2);
    cudaGetSymbolAddress((void**)&p3, g_p3);

    cudaFuncSetAttribute(mma_gemm<1>, cudaFuncAttributeMaxDynamicSharedMemorySize, SMEM_SZ);
    cudaFuncSetAttribute(mma_gemm<0>, cudaFuncAttributeMaxDynamicSharedMemorySize, SMEM_SZ);

    // GEMM1: [128,2048]@[2048,2048]  32 n-tiles x 4 splits (kLen=512), 3-pass
    mma_gemm<1><<<dim3(32, 4), 256, SMEM_SZ>>>(inputs, W1, p1, nullptr, 2048, 2048, 512, 0, 0);
    reduce_bias_act<4><<<256, 256>>>(p1, b1, h1, 2048, 1);

    // GEMM2: [128,2048]@[2048,1024]  16 x 8 (kLen=256)
    mma_gemm<1><<<dim3(16, 8), 256, SMEM_SZ>>>(h1, W2, p2, nullptr, 1024, 2048, 256, 0, 0);
    reduce_bias_act<8><<<128, 256>>>(p2, b2, h2, 1024, 1);

    // GEMM3: [128,1024]@[1024,1024]  16 x 8 (kLen=128)
    mma_gemm<1><<<dim3(16, 8), 256, SMEM_SZ>>>(h2, W3, p3, nullptr, 1024, 1024, 128, 0, 0);
    reduce_bias_act<8><<<128, 256>>>(p3, b3, h3, 1024, 1);

    // GEMM4: [128,1024]@[1024,10240]  160 n-tiles, NO split, fused epilogue
    mma_gemm<0><<<dim3(160, 1), 256, SMEM_SZ>>>(h3, T, Mv, nullptr, 10240, 1024, 1024, 1, 0);

    mbd_kernel<<<512, 128>>>(Mv, ob);
    final_kernel<<<BATCH, 128>>>(h3, ob, Wc, bc, out);
}

// round 5
// speedup vs baseline: 4.1484x; 1.4211x over previous
#include <cuda_runtime.h>
#include <cuda_bf16.h>
#include <cstdint>

#define BATCH 128

// ---------------- element counts --------------------------------------------
static constexpr int E_IN = 128 * 2048;
static constexpr int E_W1 = 2048 * 2048;
static constexpr int E_W2 = 2048 * 1024;
static constexpr int E_W3 = 1024 * 1024;
static constexpr int E_T  = 1024 * 10240;

// ---------------- scratch (__device__ globals, 16B aligned) -----------------
__device__ __align__(16) uint16_t g_inh[E_IN], g_inl[E_IN];
__device__ __align__(16) uint16_t g_w1h[E_W1], g_w1l[E_W1];
__device__ __align__(16) uint16_t g_w2h[E_W2], g_w2l[E_W2];
__device__ __align__(16) uint16_t g_w3h[E_W3], g_w3l[E_W3];
__device__ __align__(16) uint16_t g_th [E_T];
__device__ __align__(16) uint16_t g_h1h[128 * 2048], g_h1l[128 * 2048];
__device__ __align__(16) uint16_t g_h2h[128 * 1024], g_h2l[128 * 1024];
__device__ __align__(16) uint16_t g_h3h[128 * 1024];
__device__ __align__(16) float g_h3[128 * 1024];
__device__ __align__(16) float g_M [128 * 10240];
__device__ __align__(16) float g_ob[128 * 512];
__device__ __align__(16) float g_p1[4 * 128 * 2048];
__device__ __align__(16) float g_p2[8 * 128 * 1024];
__device__ __align__(16) float g_p3[8 * 128 * 1024];

// ---------------- helpers ----------------------------------------------------
__device__ __forceinline__ uint32_t smem_u32(const void* p) {
    uint32_t a;
    asm("{ .reg .u64 t; cvta.to.shared.u64 t, %1; cvt.u32.u64 %0, t; }"
        : "=r"(a) : "l"(p));
    return a;
}
__device__ __forceinline__ void ldsm_x4(uint32_t* r, uint32_t addr) {
    asm volatile("ldmatrix.sync.aligned.m8n8.x4.shared.b16 {%0,%1,%2,%3}, [%4];"
        : "=r"(r[0]), "=r"(r[1]), "=r"(r[2]), "=r"(r[3]) : "r"(addr));
}
__device__ __forceinline__ void ldsm_x4_t(uint32_t* r, uint32_t addr) {
    asm volatile("ldmatrix.sync.aligned.m8n8.x4.trans.shared.b16 {%0,%1,%2,%3}, [%4];"
        : "=r"(r[0]), "=r"(r[1]), "=r"(r[2]), "=r"(r[3]) : "r"(addr));
}
__device__ __forceinline__ void mma16816(float* d, const uint32_t* a,
                                         uint32_t b0, uint32_t b1) {
    asm volatile(
        "mma.sync.aligned.m16n8k16.row.col.f32.bf16.bf16.f32 "
        "{%0,%1,%2,%3}, {%4,%5,%6,%7}, {%8,%9}, {%0,%1,%2,%3};"
        : "+f"(d[0]), "+f"(d[1]), "+f"(d[2]), "+f"(d[3])
        : "r"(a[0]), "r"(a[1]), "r"(a[2]), "r"(a[3]), "r"(b0), "r"(b1));
}
__device__ __forceinline__ void cpa16(uint32_t dst, const void* src) {
    asm volatile("cp.async.cg.shared.global [%0], [%1], 16;" :: "r"(dst), "l"(src));
}
#define CP_COMMIT() asm volatile("cp.async.commit_group;" ::: "memory")
#define CP_WAIT2()  asm volatile("cp.async.wait_group 2;"  ::: "memory")

__device__ __forceinline__ uint32_t pack_hi(float f0, float f1) {
    __nv_bfloat16 b0 = __float2bfloat16(f0);
    __nv_bfloat16 b1 = __float2bfloat16(f1);
    return ((uint32_t)__bfloat16_as_ushort(b1) << 16) | __bfloat16_as_ushort(b0);
}
__device__ __forceinline__ uint32_t pack_lo(float f0, float f1) {
    __nv_bfloat16 b0 = __float2bfloat16(f0);
    __nv_bfloat16 b1 = __float2bfloat16(f1);
    __nv_bfloat16 c0 = __float2bfloat16(f0 - __bfloat162float(b0));
    __nv_bfloat16 c1 = __float2bfloat16(f1 - __bfloat162float(b1));
    return ((uint32_t)__bfloat16_as_ushort(c1) << 16) | __bfloat16_as_ushort(c0);
}

// ---------------- fp32 -> bf16 hi/lo conversion (all static inputs) ---------
__global__ __launch_bounds__(256)
void convert_all(const float* __restrict__ in, const float* __restrict__ W1,
                 const float* __restrict__ W2, const float* __restrict__ W3,
                 const float* __restrict__ T)
{
    const int o1 = E_IN / 4, o2 = o1 + E_W1 / 4, o3 = o2 + E_W2 / 4;
    const int o4 = o3 + E_W3 / 4, o5 = o4 + E_T / 4;
    int i4 = blockIdx.x * 256 + threadIdx.x;
    if (i4 >= o5) return;
    const float4* src; uint2* oh; uint2* ol; int li;
    if (i4 < o1)      { li = i4;      src = (const float4*)in; oh = (uint2*)g_inh; ol = (uint2*)g_inl; }
    else if (i4 < o2) { li = i4 - o1; src = (const float4*)W1; oh = (uint2*)g_w1h; ol = (uint2*)g_w1l; }
    else if (i4 < o3) { li = i4 - o2; src = (const float4*)W2; oh = (uint2*)g_w2h; ol = (uint2*)g_w2l; }
    else if (i4 < o4) { li = i4 - o3; src = (const float4*)W3; oh = (uint2*)g_w3h; ol = (uint2*)g_w3l; }
    else              { li = i4 - o4; src = (const float4*)T;  oh = (uint2*)g_th;  ol = nullptr; }
    float4 f = src[li];
    oh[li] = make_uint2(pack_hi(f.x, f.y), pack_hi(f.z, f.w));
    if (ol) ol[li] = make_uint2(pack_lo(f.x, f.y), pack_lo(f.z, f.w));
}

// ---------------- GEMM: M128 x N64, BK=32, cp.async 3-stage ring -------------
static constexpr int A_STRB = 80;    // bytes/row: 32 bf16 = 64B + 16B pad
static constexpr int B_STRB = 144;   // bytes/row: 64 bf16 = 128B + 16B pad

template <int THREE> struct Geo {
    static constexpr int A_BYTES = 128 * A_STRB;               // 10240
    static constexpr int B_BYTES = 32 * B_STRB;                // 4608
    static constexpr int AL_OFF  = A_BYTES;                    // (used iff THREE)
    static constexpr int BH_OFF  = (THREE ? 2 : 1) * A_BYTES;
    static constexpr int BL_OFF  = BH_OFF + B_BYTES;
    static constexpr int STAGE   = (THREE ? 2 : 1) * (A_BYTES + B_BYTES);
    static constexpr int SMEM    = 3 * STAGE;
};

template <int THREE>
__global__ __launch_bounds__(256, 2)
void mma_gemm(const uint16_t* __restrict__ aH, const uint16_t* __restrict__ aL,
              const uint16_t* __restrict__ wH, const uint16_t* __restrict__ wL,
              float* __restrict__ outp, const float* __restrict__ bias,
              int Ncols, int K, int kLen, int fuse, int lrelu)
{
    extern __shared__ __align__(128) char sm[];
    using G = Geo<THREE>;
    const uint32_t smB = smem_u32(sm);
    const int tid = threadIdx.x, lane = tid & 31, wid = tid >> 5;
    const int wm = (wid & 3) * 32, wn = (wid >> 2) * 32;
    const int n0 = blockIdx.x * 64;
    const int kStart = blockIdx.y * kLen;
    const int nIter = kLen >> 5;

    const int aR = tid >> 2, aS = tid & 3;      // A: chunks tid and tid+256
    const int bR = tid >> 3, bS = tid & 7;      // B: chunk tid

    auto ISSUE = [&](int sidx) {
        if (sidx < nIter) {
            const int kOff = kStart + sidx * 32;
            const uint32_t st = smB + (sidx % 3) * G::STAGE;
            cpa16(st + aR * A_STRB + aS * 16,          aH + (size_t)aR * K + kOff + aS * 8);
            cpa16(st + (aR + 64) * A_STRB + aS * 16,   aH + (size_t)(aR + 64) * K + kOff + aS * 8);
            if (THREE) {
                cpa16(st + G::AL_OFF + aR * A_STRB + aS * 16,
                      aL + (size_t)aR * K + kOff + aS * 8);
                cpa16(st + G::AL_OFF + (aR + 64) * A_STRB + aS * 16,
                      aL + (size_t)(aR + 64) * K + kOff + aS * 8);
            }
            cpa16(st + G::BH_OFF + bR * B_STRB + bS * 16,
                  wH + (size_t)(kOff + bR) * Ncols + n0 + bS * 8);
            if (THREE)
                cpa16(st + G::BL_OFF + bR * B_STRB + bS * 16,
                      wL + (size_t)(kOff + bR) * Ncols + n0 + bS * 8);
        }
        CP_COMMIT();
    };

    float acc[2][4][4];
    #pragma unroll
    for (int i = 0; i < 2; i++)
        #pragma unroll
        for (int j = 0; j < 4; j++)
            #pragma unroll
            for (int c = 0; c < 4; c++) acc[i][j][c] = 0.0f;

    ISSUE(0); ISSUE(1); ISSUE(2);

    for (int it = 0; it < nIter; ++it) {
        CP_WAIT2();
        __syncthreads();
        const uint32_t st = smB + (it % 3) * G::STAGE;
        const uint32_t asHi = st, asLo = st + G::AL_OFF;
        const uint32_t bsHi = st + G::BH_OFF, bsLo = st + G::BL_OFF;

        #pragma unroll
        for (int kk = 0; kk < 32; kk += 16) {
            const uint32_t arow = wm + (lane & 15);
            const uint32_t acol = kk + ((lane >> 4) << 3);
            uint32_t ah[2][4], al[2][4];
            #pragma unroll
            for (int mt = 0; mt < 2; mt++) {
                uint32_t off = (arow + mt * 16) * A_STRB + acol * 2;
                ldsm_x4(ah[mt], asHi + off);
                if (THREE) ldsm_x4(al[mt], asLo + off);
            }
            uint32_t bh[4][2], bl[4][2];
            #pragma unroll
            for (int np = 0; np < 2; np++) {
                const uint32_t brow = kk + (lane & 15);
                const uint32_t bcol = wn + np * 16 + ((lane >> 4) << 3);
                uint32_t off = brow * B_STRB + bcol * 2;
                uint32_t r4[4];
                ldsm_x4_t(r4, bsHi + off);
                bh[np*2][0] = r4[0]; bh[np*2][1] = r4[1];
                bh[np*2+1][0] = r4[2]; bh[np*2+1][1] = r4[3];
                if (THREE) {
                    ldsm_x4_t(r4, bsLo + off);
                    bl[np*2][0] = r4[0]; bl[np*2][1] = r4[1];
                    bl[np*2+1][0] = r4[2]; bl[np*2+1][1] = r4[3];
                }
            }
            #pragma unroll
            for (int mt = 0; mt < 2; mt++)
                #pragma unroll
                for (int nt = 0; nt < 4; nt++) {
                    mma16816(acc[mt][nt], ah[mt], bh[nt][0], bh[nt][1]);
                    if (THREE) {
                        mma16816(acc[mt][nt], ah[mt], bl[nt][0], bl[nt][1]);
                        mma16816(acc[mt][nt], al[mt], bh[nt][0], bh[nt][1]);
                    }
                }
        }
        __syncthreads();
        ISSUE(it + 3);
    }

    // ---- epilogue ----
    float* pbase = fuse ? outp
                        : outp + (size_t)blockIdx.y * BATCH * (size_t)Ncols;
    const int g  = lane >> 2;
    const int c2 = (lane & 3) * 2;
    #pragma unroll
    for (int mt = 0; mt < 2; mt++)
        #pragma unroll
        for (int nt = 0; nt < 4; nt++) {
            const int m = wm + mt * 16 + g;
            const int n = n0 + wn + nt * 8 + c2;
            float v0 = acc[mt][nt][0], v1 = acc[mt][nt][1];
            float v2 = acc[mt][nt][2], v3 = acc[mt][nt][3];
            if (fuse) {
                if (bias) { float b0 = bias[n], b1 = bias[n+1];
                            v0 += b0; v1 += b1; v2 += b0; v3 += b1; }
                if (lrelu) {
                    v0 = (v0 >= 0.f) ? v0 : 0.01f * v0;
                    v1 = (v1 >= 0.f) ? v1 : 0.01f * v1;
                    v2 = (v2 >= 0.f) ? v2 : 0.01f * v2;
                    v3 = (v3 >= 0.f) ? v3 : 0.01f * v3;
                }
            }
            *(float2*)&pbase[(size_t)m * Ncols + n]       = make_float2(v0, v1);
            *(float2*)&pbase[(size_t)(m + 8) * Ncols + n] = make_float2(v2, v3);
        }
}

// -------- split-K reduce + bias + lrelu + bf16 hi/lo re-pack -----------------
template <int S, int WF32, int WLO>
__global__ __launch_bounds__(256)
void reduce_ba(const float* __restrict__ part, const float* __restrict__ bias,
               float* __restrict__ outf, uint16_t* __restrict__ outh,
               uint16_t* __restrict__ outl, int Ncols)
{
    const int i4 = blockIdx.x * 256 + threadIdx.x;
    const int E4 = BATCH * Ncols / 4;
    if (i4 >= E4) return;
    const float4* p4 = (const float4*)part;
    float4 v[S];
    #pragma unroll
    for (int sp = 0; sp < S; sp++) v[sp] = p4[(size_t)sp * E4 + i4];
    float4 s = v[0];
    #pragma unroll
    for (int sp = 1; sp < S; sp++) {
        s.x += v[sp].x; s.y += v[sp].y; s.z += v[sp].z; s.w += v[sp].w;
    }
    const int col = (i4 * 4) % Ncols;
    s.x += bias[col]; s.y += bias[col+1]; s.z += bias[col+2]; s.w += bias[col+3];
    s.x = (s.x >= 0.f) ? s.x : 0.01f * s.x;
    s.y = (s.y >= 0.f) ? s.y : 0.01f * s.y;
    s.z = (s.z >= 0.f) ? s.z : 0.01f * s.z;
    s.w = (s.w >= 0.f) ? s.w : 0.01f * s.w;
    if (WF32) ((float4*)outf)[i4] = s;
    ((uint2*)outh)[i4] = make_uint2(pack_hi(s.x, s.y), pack_hi(s.z, s.w));
    if (WLO) ((uint2*)outl)[i4] = make_uint2(pack_lo(s.x, s.y), pack_lo(s.z, s.w));
}

// ---------------- minibatch discrimination -----------------------------------
__global__ __launch_bounds__(128) void mbd_kernel(
    const float* __restrict__ Mv, float* __restrict__ ob)
{
    const int o = blockIdx.x;
    const int b = threadIdx.x;
    __shared__ float Ms[BATCH * 20];

    #pragma unroll
    for (int i = 0; i < 20; i++) {
        int idx = b + i * BATCH;
        int a = idx / 20, k = idx % 20;
        Ms[a * 20 + k] = Mv[(size_t)a * 10240 + o * 20 + k];
    }
    __syncthreads();

    float my[20];
    #pragma unroll
    for (int k = 0; k < 20; k++) my[k] = Ms[b * 20 + k];

    float acc = 0.0f;
    for (int a = 0; a < BATCH; a++) {
        float s = 0.0f;
        #pragma unroll
        for (int k = 0; k < 20; k++)
            s += fabsf(Ms[a * 20 + k] - my[k]);
        acc += __expf(-s);
    }
    ob[(size_t)b * 512 + o] = acc - 1.0f;
}

__global__ __launch_bounds__(128) void final_kernel(
    const float* __restrict__ h3, const float* __restrict__ ob,
    const float* __restrict__ Wc, const float* __restrict__ bc,
    float* __restrict__ out)
{
    const int b = blockIdx.x;
    const int tid = threadIdx.x;

    float s = 0.0f;
    for (int j = tid; j < 1024; j += 128)
        s += h3[(size_t)b * 1024 + j] * Wc[j];
    for (int o = tid; o < 512; o += 128)
        s += ob[(size_t)b * 512 + o] * Wc[1024 + o];

    __shared__ float red[128];
    red[tid] = s;
    __syncthreads();
    #pragma unroll
    for (int st = 64; st > 0; st >>= 1) {
        if (tid < st) red[tid] += red[tid + st];
        __syncthreads();
    }
    if (tid == 0) out[b] = red[0] + bc[0];
}

// ---------------------------------------------------------------------------
extern "C" void kernel_launch(void* const* d_in, const int* in_sizes, int n_in,
                              void* d_out, int out_size)
{
    const float* inputs = (const float*)d_in[0];
    const float* W1     = (const float*)d_in[1];
    const float* b1     = (const float*)d_in[2];
    const float* W2     = (const float*)d_in[3];
    const float* b2     = (const float*)d_in[4];
    const float* W3     = (const float*)d_in[5];
    const float* b3     = (const float*)d_in[6];
    const float* T      = (const float*)d_in[7];
    const float* Wc     = (const float*)d_in[8];
    const float* bc     = (const float*)d_in[9];
    float* out = (float*)d_out;

    uint16_t *inh, *inl, *w1h, *w1l, *w2h, *w2l, *w3h, *w3l, *th;
    uint16_t *h1h, *h1l, *h2h, *h2l, *h3h;
    float *h3, *Mv, *ob, *p1, *p2, *p3;
    cudaGetSymbolAddress((void**)&inh, g_inh); cudaGetSymbolAddress((void**)&inl, g_inl);
    cudaGetSymbolAddress((void**)&w1h, g_w1h); cudaGetSymbolAddress((void**)&w1l, g_w1l);
    cudaGetSymbolAddress((void**)&w2h, g_w2h); cudaGetSymbolAddress((void**)&w2l, g_w2l);
    cudaGetSymbolAddress((void**)&w3h, g_w3h); cudaGetSymbolAddress((void**)&w3l, g_w3l);
    cudaGetSymbolAddress((void**)&th,  g_th);
    cudaGetSymbolAddress((void**)&h1h, g_h1h); cudaGetSymbolAddress((void**)&h1l, g_h1l);
    cudaGetSymbolAddress((void**)&h2h, g_h2h); cudaGetSymbolAddress((void**)&h2l, g_h2l);
    cudaGetSymbolAddress((void**)&h3h, g_h3h);
    cudaGetSymbolAddress((void**)&h3,  g_h3);
    cudaGetSymbolAddress((void**)&Mv,  g_M);
    cudaGetSymbolAddress((void**)&ob,  g_ob);
    cudaGetSymbolAddress((void**)&p1,  g_p1);
    cudaGetSymbolAddress((void**)&p2,  g_p2);
    cudaGetSymbolAddress((void**)&p3,  g_p3);

    cudaFuncSetAttribute(mma_gemm<1>, cudaFuncAttributeMaxDynamicSharedMemorySize,
                         Geo<1>::SMEM);
    cudaFuncSetAttribute(mma_gemm<0>, cudaFuncAttributeMaxDynamicSharedMemorySize,
                         Geo<0>::SMEM);

    // 0) convert all static fp32 inputs to bf16 hi/lo
    const int totF4 = (E_IN + E_W1 + E_W2 + E_W3 + E_T) / 4;
    convert_all<<<(totF4 + 255) / 256, 256>>>(inputs, W1, W2, W3, T);

    // 1) GEMM1: [128,2048]@[2048,2048], 32 n-tiles x 4 splits (kLen=512)
    mma_gemm<1><<<dim3(32, 4), 256, Geo<1>::SMEM>>>(
        inh, inl, w1h, w1l, p1, nullptr, 2048, 2048, 512, 0, 0);
    reduce_ba<4, 0, 1><<<256, 256>>>(p1, b1, nullptr, h1h, h1l, 2048);

    // 2) GEMM2: [128,2048]@[2048,1024], 16 x 8 (kLen=256)
    mma_gemm<1><<<dim3(16, 8), 256, Geo<1>::SMEM>>>(
        h1h, h1l, w2h, w2l, p2, nullptr, 1024, 2048, 256, 0, 0);
    reduce_ba<8, 0, 1><<<128, 256>>>(p2, b2, nullptr, h2h, h2l, 1024);

    // 3) GEMM3: [128,1024]@[1024,1024], 16 x 8 (kLen=128)
    mma_gemm<1><<<dim3(16, 8), 256, Geo<1>::SMEM>>>(
        h2h, h2l, w3h, w3l, p3, nullptr, 1024, 1024, 128, 0, 0);
    reduce_ba<8, 1, 0><<<128, 256>>>(p3, b3, h3, h3h, nullptr, 1024);

    // 4) GEMM4: [128,1024]@[1024,10240], 160 n-tiles, no split, fused epilogue
    mma_gemm<0><<<dim3(160, 1), 256, Geo<0>::SMEM>>>(
        h3h, nullptr, th, nullptr, Mv, nullptr, 10240, 1024, 1024, 1, 0);

    mbd_kernel<<<512, 128>>>(Mv, ob);
    final_kernel<<<BATCH, 128>>>(h3, ob, Wc, bc, out);
}